// round 13
// baseline (speedup 1.0000x reference)
#include <cuda_runtime.h>
#include <cuda_fp16.h>
#include <math.h>

#define DIN  128
#define DH   128
#define DOUT 16
#define NCAP 100352
#define ECAP 1600128

// ---- scratch (static __device__ per harness rules) ----
__device__ int   g_is64;            // 1 if edge_index is int64, 0 if int32
__device__ int   g_deg[NCAP];
__device__ float g_dinv[NCAP];
__device__ int   g_rowptr[NCAP + 1];
__device__ int   g_cursor[NCAP];
__device__ int   g_col[ECAP];
__device__ volatile int g_blkagg[128];   // lookback: per-block degree sums
__device__ volatile int g_blkflag[128];  // lookback: publish flags
__device__ __align__(16) __half g_h1h[(size_t)NCAP * DH];  // (x@W1)*dinv[row], fp16
__device__ __align__(16) float  g_h2[(size_t)NCAP * DOUT]; // (a1@W2)*dinv[row]

union H4 { __half2 h2[2]; uint2 u; };   // 8B  (gather granule per lane)
union H8 { __half2 h2[4]; uint4 u; };   // 16B (store granule per thread)

// ------------------------------------------------------------------
// init: zero degree array + lookback flags; block 0 detects edge dtype
// (int64 => high word of every entry is 0 since indices < 100K).
__global__ void k_init(const int* __restrict__ ei32, int e, int n) {
    int i = blockIdx.x * blockDim.x + threadIdx.x;
    if (i < n) g_deg[i] = 0;
    if (i < 128) g_blkflag[i] = 0;
    if (blockIdx.x == 0) {
        __shared__ int nz;
        if (threadIdx.x == 0) nz = 0;
        __syncthreads();
        int lim = (e < 4096) ? e : 4096;
        for (int t = threadIdx.x; t < lim; t += blockDim.x)
            if (ei32[2 * t + 1] != 0) nz = 1;   // benign race
        __syncthreads();
        if (threadIdx.x == 0) g_is64 = (nz == 0) ? 1 : 0;
    }
}

__device__ __forceinline__ int edge_at(const void* ei, size_t pos) {
    if (g_is64) return (int)((const long long*)ei)[pos];
    return ((const int*)ei)[pos];
}

__global__ void k_degree(const void* __restrict__ ei, int e, int n) {
    int i = blockIdx.x * blockDim.x + threadIdx.x;
    if (i < e) {
        int d = edge_at(ei, (size_t)e + i);
        if ((unsigned)d < (unsigned)n) atomicAdd(&g_deg[d], 1);
    }
}

// ------------------------------------------------------------------
// Fused prefix-sum: block-local inclusive scan + decoupled lookback for
// the global offset, then writes dinv, rowptr, cursor in one kernel.
// 98 blocks of 1024 — all resident on 148 SMs, so the spin is safe.
__global__ void k_scanall(int n, int nb) {
    __shared__ int s[1024];
    __shared__ int boff_sh;
    int bid = blockIdx.x, tid = threadIdx.x;
    int i = bid * 1024 + tid;
    int d = (i < n) ? g_deg[i] : 0;
    s[tid] = d;
    if (i < n) g_dinv[i] = rsqrtf((float)(d + 1)); // +1 self loop
    __syncthreads();
    for (int off = 1; off < 1024; off <<= 1) {
        int t = (tid >= off) ? s[tid - off] : 0;
        __syncthreads();
        s[tid] += t;
        __syncthreads();
    }
    int incl = s[tid];
    int blocksum = s[1023];
    if (tid == 0) {
        g_blkagg[bid] = blocksum;
        __threadfence();
        g_blkflag[bid] = 1;
        int off = 0;
        for (int p = 0; p < bid; p++) {
            while (g_blkflag[p] == 0) { }
            off += g_blkagg[p];
        }
        boff_sh = off;
    }
    __syncthreads();
    int boff = boff_sh;
    if (i < n) {
        int v = boff + incl - d;   // exclusive
        g_rowptr[i] = v;
        g_cursor[i] = v;
    }
    if (bid == nb - 1 && tid == 1023) g_rowptr[n] = boff + blocksum;
}

// ------------------------------------------------------------------
// FMA4: acc += scal * vec  (parameter names must NOT collide with x/y/z/w)
#define FMA4(acc, vec, scal) do { \
    (acc).x = fmaf((scal), (vec).x, (acc).x); \
    (acc).y = fmaf((scal), (vec).y, (acc).y); \
    (acc).z = fmaf((scal), (vec).z, (acc).z); \
    (acc).w = fmaf((scal), (vec).w, (acc).w); } while (0)

#define KC 32          // k-chunk size for GEMM1
#define GF_BLOCKS 256  // CSR-fill blocks placed FIRST in the fused grid

// Fused: blocks [0, GF_BLOCKS) do the CSR fill; blocks [GF_BLOCKS, ...)
// do GEMM1: h1h = fp16((x @ W1) * dinv[row]).
__global__ void __launch_bounds__(256, 1) k_fill_gemm1(const float* __restrict__ x,
                                                       const float* __restrict__ W1,
                                                       const void* __restrict__ ei,
                                                       int e, int n) {
    __shared__ float Ws[KC * DH];    // 16KB
    __shared__ float Xs[128 * KC];   // 16KB

    if (blockIdx.x < GF_BLOCKS) {
        int i0 = blockIdx.x * blockDim.x + threadIdx.x;
        int stride = GF_BLOCKS * blockDim.x;
        for (int i = i0; i < e; i += stride) {
            int s = edge_at(ei, (size_t)i);
            int d = edge_at(ei, (size_t)e + i);
            if ((unsigned)s < (unsigned)n && (unsigned)d < (unsigned)n) {
                int p = atomicAdd(&g_cursor[d], 1);
                if ((unsigned)p < (unsigned)ECAP) g_col[p] = s;
            }
        }
        return;
    }

    int row0 = (blockIdx.x - GF_BLOCKS) * 128;
    int tx = threadIdx.x & 15;
    int ty = threadIdx.x >> 4;
    float4 a0[8], a1[8];
    #pragma unroll
    for (int r = 0; r < 8; r++) { a0[r] = make_float4(0,0,0,0); a1[r] = make_float4(0,0,0,0); }

    const float4* W4 = (const float4*)W1;
    const float4* x4 = (const float4*)x;
    float4* Ws4 = (float4*)Ws;
    float4* Xs4 = (float4*)Xs;

    for (int kc = 0; kc < DIN / KC; kc++) {
        for (int i = threadIdx.x; i < KC * DH / 4; i += 256)
            Ws4[i] = W4[kc * (KC * DH / 4) + i];
        for (int i = threadIdx.x; i < 128 * KC / 4; i += 256) {
            int r = i >> 3, c = i & 7, gr = row0 + r;
            Xs4[i] = (gr < n) ? x4[(size_t)gr * 32 + kc * 8 + c]
                              : make_float4(0.f, 0.f, 0.f, 0.f);
        }
        __syncthreads();

        const float* wp = Ws + tx * 8;
        #pragma unroll
        for (int k = 0; k < KC; k++) {
            float4 wv0 = *(const float4*)(wp + k * 128);
            float4 wv1 = *(const float4*)(wp + k * 128 + 4);
            #pragma unroll
            for (int r = 0; r < 8; r++) {
                float xv = Xs[(ty * 8 + r) * KC + k];
                FMA4(a0[r], wv0, xv);
                FMA4(a1[r], wv1, xv);
            }
        }
        __syncthreads();
    }

    #pragma unroll
    for (int r = 0; r < 8; r++) {
        int row = row0 + ty * 8 + r;
        if (row < n) {
            float dv = g_dinv[row];
            float4 o0 = a0[r], o1 = a1[r];
            o0.x *= dv; o0.y *= dv; o0.z *= dv; o0.w *= dv;
            o1.x *= dv; o1.y *= dv; o1.z *= dv; o1.w *= dv;
            H8 st;
            st.h2[0] = __floats2half2_rn(o0.x, o0.y);
            st.h2[1] = __floats2half2_rn(o0.z, o0.w);
            st.h2[2] = __floats2half2_rn(o1.x, o1.y);
            st.h2[3] = __floats2half2_rn(o1.z, o1.w);
            *(uint4*)(g_h1h + (size_t)row * DH + tx * 8) = st.u;
        }
    }
}

// ------------------------------------------------------------------
// Fused Agg1 + GEMM2: warp per node, fp16 gather, x8 unroll.
__device__ __forceinline__ void acc_h4(float4& acc, uint2 raw) {
    H4 t; t.u = raw;
    float2 f0 = __half22float2(t.h2[0]);
    float2 f1 = __half22float2(t.h2[1]);
    acc.x += f0.x; acc.y += f0.y; acc.z += f1.x; acc.w += f1.y;
}

__global__ void __launch_bounds__(256, 3) k_agg1_gemm2(const float* __restrict__ b1,
                                                       const float* __restrict__ W2, int n) {
    __shared__ float W2s[DH * DOUT]; // 8KB
    for (int i = threadIdx.x; i < DH * DOUT; i += blockDim.x) W2s[i] = W2[i];
    __syncthreads();

    int warp = (blockIdx.x * blockDim.x + threadIdx.x) >> 5;
    int lane = threadIdx.x & 31;
    if (warp >= n) return;

    int beg = g_rowptr[warp], end = g_rowptr[warp + 1];
    const uint2* h8 = (const uint2*)g_h1h;     // 8B granules; row = 32 granules
    float4 acc = make_float4(0.f, 0.f, 0.f, 0.f);
    acc_h4(acc, h8[(size_t)warp * 32 + lane]); // self (already *dinv[i])

    int e = beg;
    for (; e + 7 < end; e += 8) {
        int j0 = g_col[e],     j1 = g_col[e + 1], j2 = g_col[e + 2], j3 = g_col[e + 3];
        int j4 = g_col[e + 4], j5 = g_col[e + 5], j6 = g_col[e + 6], j7 = g_col[e + 7];
        uint2 v0 = h8[(size_t)j0 * 32 + lane];
        uint2 v1 = h8[(size_t)j1 * 32 + lane];
        uint2 v2 = h8[(size_t)j2 * 32 + lane];
        uint2 v3 = h8[(size_t)j3 * 32 + lane];
        uint2 v4 = h8[(size_t)j4 * 32 + lane];
        uint2 v5 = h8[(size_t)j5 * 32 + lane];
        uint2 v6 = h8[(size_t)j6 * 32 + lane];
        uint2 v7 = h8[(size_t)j7 * 32 + lane];
        acc_h4(acc, v0); acc_h4(acc, v1); acc_h4(acc, v2); acc_h4(acc, v3);
        acc_h4(acc, v4); acc_h4(acc, v5); acc_h4(acc, v6); acc_h4(acc, v7);
    }
    for (; e < end; e++) {
        int j = g_col[e];
        acc_h4(acc, h8[(size_t)j * 32 + lane]);
    }

    float di = g_dinv[warp];
    float4 b = ((const float4*)b1)[lane];
    float xs[4];
    xs[0] = fmaxf(fmaf(acc.x, di, b.x), 0.f);
    xs[1] = fmaxf(fmaf(acc.y, di, b.y), 0.f);
    xs[2] = fmaxf(fmaf(acc.z, di, b.z), 0.f);
    xs[3] = fmaxf(fmaf(acc.w, di, b.w), 0.f);

    // gemm2: register-resident a1 row; lane l owns k=4l..4l+3
    float4 c0 = make_float4(0,0,0,0), c1 = c0, c2 = c0, c3 = c0;
    int k0 = lane * 4;
    #pragma unroll
    for (int kk = 0; kk < 4; kk++) {
        const float4* wrow = (const float4*)(W2s + (k0 + kk) * DOUT);
        float s = xs[kk];
        float4 q0 = wrow[0], q1 = wrow[1], q2 = wrow[2], q3 = wrow[3];
        FMA4(c0, q0, s);
        FMA4(c1, q1, s);
        FMA4(c2, q2, s);
        FMA4(c3, q3, s);
    }
    float v[16] = {c0.x,c0.y,c0.z,c0.w, c1.x,c1.y,c1.z,c1.w,
                   c2.x,c2.y,c2.z,c2.w, c3.x,c3.y,c3.z,c3.w};
    #pragma unroll
    for (int off = 16; off >= 1; off >>= 1) {
        #pragma unroll
        for (int o = 0; o < 16; o++)
            v[o] += __shfl_xor_sync(0xffffffffu, v[o], off);
    }
    if (lane < 16)
        g_h2[(size_t)warp * DOUT + lane] = v[lane] * di;
}

// ------------------------------------------------------------------
// Agg2 + bias + log_softmax. Warp per node; two half-warps split edges,
// each unrolled x4.
__global__ void k_agg2(const float* __restrict__ b2, float* __restrict__ out, int n) {
    int warp = (blockIdx.x * blockDim.x + threadIdx.x) >> 5;
    int lane = threadIdx.x & 31;
    if (warp >= n) return;
    int c = lane & 15, half = lane >> 4;
    int beg = g_rowptr[warp], end = g_rowptr[warp + 1];
    float acc = (half == 0) ? g_h2[(size_t)warp * DOUT + c] : 0.f; // self
    int e = beg + half;
    for (; e + 6 < end; e += 8) {
        int j0 = g_col[e], j1 = g_col[e + 2], j2 = g_col[e + 4], j3 = g_col[e + 6];
        float u0 = g_h2[(size_t)j0 * DOUT + c];
        float u1 = g_h2[(size_t)j1 * DOUT + c];
        float u2 = g_h2[(size_t)j2 * DOUT + c];
        float u3 = g_h2[(size_t)j3 * DOUT + c];
        acc += (u0 + u1) + (u2 + u3);
    }
    for (; e < end; e += 2) {
        int j = g_col[e];
        acc += g_h2[(size_t)j * DOUT + c];
    }
    acc += __shfl_xor_sync(0xffffffffu, acc, 16);
    float di = g_dinv[warp];
    float logit = fmaf(acc, di, b2[c]);
    float m = logit;
    #pragma unroll
    for (int off = 8; off >= 1; off >>= 1)
        m = fmaxf(m, __shfl_xor_sync(0xffffffffu, m, off));
    float ex = expf(logit - m);
    float s = ex;
    #pragma unroll
    for (int off = 8; off >= 1; off >>= 1)
        s += __shfl_xor_sync(0xffffffffu, s, off);
    if (half == 0)
        out[(size_t)warp * DOUT + c] = logit - m - logf(s);
}

// ------------------------------------------------------------------
extern "C" void kernel_launch(void* const* d_in, const int* in_sizes, int n_in,
                              void* d_out, int out_size) {
    const float* x  = (const float*)d_in[0];
    const void*  ei = d_in[1];                 // int32 or int64, detected on device
    const float* W1 = (const float*)d_in[2];
    const float* b1 = (const float*)d_in[3];
    const float* W2 = (const float*)d_in[4];
    const float* b2 = (const float*)d_in[5];
    float* out = (float*)d_out;

    int n = in_sizes[0] / DIN;  // 100000
    int e = in_sizes[1] / 2;    // 1600000

    // graph build (3 launches), then fill_gemm1 sits at profile slot #4
    k_init   <<<(n + 255) / 256, 256>>>((const int*)ei, e, n);
    k_degree <<<(e + 255) / 256, 256>>>(ei, e, n);
    int nb = (n + 1023) / 1024;
    k_scanall<<<nb, 1024>>>(n, nb);

    int g1 = (n + 127) / 128;
    k_fill_gemm1<<<GF_BLOCKS + g1, 256>>>(x, W1, ei, e, n);

    // fused layer-1 aggregation (fp16 gather) + layer-2 GEMM
    k_agg1_gemm2<<<(n + 7) / 8, 256>>>(b1, W2, n);

    // layer-2 aggregation + log_softmax
    k_agg2<<<(n + 7) / 8, 256>>>(b2, out, n);
}

// round 14
// speedup vs baseline: 1.1086x; 1.1086x over previous
#include <cuda_runtime.h>
#include <cuda_fp16.h>
#include <math.h>

#define DIN  128
#define DH   128
#define DOUT 16
#define NCAP 100352
#define ECAP 1600128

// ---- scratch (static __device__ per harness rules) ----
__device__ int   g_is64;            // 1 if edge_index is int64, 0 if int32
__device__ int   g_deg[NCAP];
__device__ float g_dinv[NCAP];
__device__ int   g_rowptr[NCAP + 1];
__device__ int   g_cursor[NCAP];
__device__ int   g_col[ECAP];
__device__ volatile int g_blkagg[128];   // lookback: per-block degree sums
__device__ volatile int g_blkflag[128];  // lookback: publish flags
__device__ __align__(16) __half g_h1h[(size_t)NCAP * DH];  // (x@W1)*dinv[row], fp16
__device__ __align__(16) float  g_h2[(size_t)NCAP * DOUT]; // (a1@W2)*dinv[row]

union H4 { __half2 h2[2]; uint2 u; };   // 8B  (gather granule per lane)
union H8 { __half2 h2[4]; uint4 u; };   // 16B (store granule per thread)

// ------------------------------------------------------------------
// init: zero degree array + lookback flags; block 0 detects edge dtype
// (int64 => high word of every entry is 0 since indices < 100K).
__global__ void k_init(const int* __restrict__ ei32, int e, int n) {
    int i = blockIdx.x * blockDim.x + threadIdx.x;
    if (i < n) g_deg[i] = 0;
    if (i < 128) g_blkflag[i] = 0;
    if (blockIdx.x == 0) {
        __shared__ int nz;
        if (threadIdx.x == 0) nz = 0;
        __syncthreads();
        int lim = (e < 4096) ? e : 4096;
        for (int t = threadIdx.x; t < lim; t += blockDim.x)
            if (ei32[2 * t + 1] != 0) nz = 1;   // benign race
        __syncthreads();
        if (threadIdx.x == 0) g_is64 = (nz == 0) ? 1 : 0;
    }
}

__device__ __forceinline__ int edge_at(const void* ei, size_t pos) {
    if (g_is64) return (int)((const long long*)ei)[pos];
    return ((const int*)ei)[pos];
}

__global__ void k_degree(const void* __restrict__ ei, int e, int n) {
    int i = blockIdx.x * blockDim.x + threadIdx.x;
    if (i < e) {
        int d = edge_at(ei, (size_t)e + i);
        if ((unsigned)d < (unsigned)n) atomicAdd(&g_deg[d], 1);
    }
}

// ------------------------------------------------------------------
// Fused prefix-sum: block-local scan + PARALLEL decoupled lookback
// (thread p < bid waits on flag[p] and fetches agg[p]; block-reduce).
// 98 blocks of 1024, all resident on 148 SMs => spin is deadlock-free.
__global__ void k_scanall(int n, int nb) {
    __shared__ int s[1024];
    __shared__ int boff_sh;
    int bid = blockIdx.x, tid = threadIdx.x;
    int i = bid * 1024 + tid;
    int d = (i < n) ? g_deg[i] : 0;
    s[tid] = d;
    if (i < n) g_dinv[i] = rsqrtf((float)(d + 1)); // +1 self loop
    __syncthreads();
    for (int off = 1; off < 1024; off <<= 1) {
        int t = (tid >= off) ? s[tid - off] : 0;
        __syncthreads();
        s[tid] += t;
        __syncthreads();
    }
    int incl = s[tid];
    int blocksum = s[1023];
    __syncthreads();                  // everyone has read s before reuse

    if (tid == 0) {                   // publish this block's sum
        g_blkagg[bid] = blocksum;
        __threadfence();
        g_blkflag[bid] = 1;
    }

    // parallel lookback: thread p (< bid) spins on flag[p], grabs agg[p]
    int part = 0;
    if (tid < bid) {
        while (g_blkflag[tid] == 0) { }
        part = g_blkagg[tid];
    }
    s[tid] = part;
    __syncthreads();
    for (int off = 512; off >= 1; off >>= 1) {
        if (tid < off) s[tid] += s[tid + off];
        __syncthreads();
    }
    if (tid == 0) boff_sh = s[0];
    __syncthreads();

    int boff = boff_sh;
    if (i < n) {
        int v = boff + incl - d;   // exclusive
        g_rowptr[i] = v;
        g_cursor[i] = v;
    }
    if (bid == nb - 1 && tid == 1023) g_rowptr[n] = boff + blocksum;
}

// ------------------------------------------------------------------
// CSR fill: one edge per thread (standalone — the fused variant measured
// slower than serial: 165us fused vs 104.8 + ~35 separate).
__global__ void k_fill(const void* __restrict__ ei, int e, int n) {
    int i = blockIdx.x * blockDim.x + threadIdx.x;
    if (i < e) {
        int s = edge_at(ei, (size_t)i);
        int d = edge_at(ei, (size_t)e + i);
        if ((unsigned)s < (unsigned)n && (unsigned)d < (unsigned)n) {
            int p = atomicAdd(&g_cursor[d], 1);
            if ((unsigned)p < (unsigned)ECAP) g_col[p] = s;
        }
    }
}

// ------------------------------------------------------------------
// FMA4: acc += scal * vec  (parameter names must NOT collide with x/y/z/w)
#define FMA4(acc, vec, scal) do { \
    (acc).x = fmaf((scal), (vec).x, (acc).x); \
    (acc).y = fmaf((scal), (vec).y, (acc).y); \
    (acc).z = fmaf((scal), (vec).z, (acc).z); \
    (acc).w = fmaf((scal), (vec).w, (acc).w); } while (0)

#define KC 32   // k-chunk size for GEMM1

// GEMM1 (proven 104.8us config): h1h = fp16((x @ W1) * dinv[row]).
__global__ void __launch_bounds__(256, 1) k_gemm1(const float* __restrict__ x,
                                                  const float* __restrict__ W1, int n) {
    __shared__ float Ws[KC * DH];    // 16KB
    __shared__ float Xs[128 * KC];   // 16KB
    int row0 = blockIdx.x * 128;

    int tx = threadIdx.x & 15;
    int ty = threadIdx.x >> 4;
    float4 a0[8], a1[8];
    #pragma unroll
    for (int r = 0; r < 8; r++) { a0[r] = make_float4(0,0,0,0); a1[r] = make_float4(0,0,0,0); }

    const float4* W4 = (const float4*)W1;
    const float4* x4 = (const float4*)x;
    float4* Ws4 = (float4*)Ws;
    float4* Xs4 = (float4*)Xs;

    for (int kc = 0; kc < DIN / KC; kc++) {
        for (int i = threadIdx.x; i < KC * DH / 4; i += 256)
            Ws4[i] = W4[kc * (KC * DH / 4) + i];
        for (int i = threadIdx.x; i < 128 * KC / 4; i += 256) {
            int r = i >> 3, c = i & 7, gr = row0 + r;
            Xs4[i] = (gr < n) ? x4[(size_t)gr * 32 + kc * 8 + c]
                              : make_float4(0.f, 0.f, 0.f, 0.f);
        }
        __syncthreads();

        const float* wp = Ws + tx * 8;
        #pragma unroll
        for (int k = 0; k < KC; k++) {
            float4 wv0 = *(const float4*)(wp + k * 128);
            float4 wv1 = *(const float4*)(wp + k * 128 + 4);
            #pragma unroll
            for (int r = 0; r < 8; r++) {
                float xv = Xs[(ty * 8 + r) * KC + k];
                FMA4(a0[r], wv0, xv);
                FMA4(a1[r], wv1, xv);
            }
        }
        __syncthreads();
    }

    #pragma unroll
    for (int r = 0; r < 8; r++) {
        int row = row0 + ty * 8 + r;
        if (row < n) {
            float dv = g_dinv[row];
            float4 o0 = a0[r], o1 = a1[r];
            o0.x *= dv; o0.y *= dv; o0.z *= dv; o0.w *= dv;
            o1.x *= dv; o1.y *= dv; o1.z *= dv; o1.w *= dv;
            H8 st;
            st.h2[0] = __floats2half2_rn(o0.x, o0.y);
            st.h2[1] = __floats2half2_rn(o0.z, o0.w);
            st.h2[2] = __floats2half2_rn(o1.x, o1.y);
            st.h2[3] = __floats2half2_rn(o1.z, o1.w);
            *(uint4*)(g_h1h + (size_t)row * DH + tx * 8) = st.u;
        }
    }
}

// ------------------------------------------------------------------
// Fused Agg1 + GEMM2: warp per node, fp16 gather, x8 unroll.
// (No occupancy cap — the (256,3) cap in R13 likely caused reg spills.)
__device__ __forceinline__ void acc_h4(float4& acc, uint2 raw) {
    H4 t; t.u = raw;
    float2 f0 = __half22float2(t.h2[0]);
    float2 f1 = __half22float2(t.h2[1]);
    acc.x += f0.x; acc.y += f0.y; acc.z += f1.x; acc.w += f1.y;
}

__global__ void __launch_bounds__(256) k_agg1_gemm2(const float* __restrict__ b1,
                                                    const float* __restrict__ W2, int n) {
    __shared__ float W2s[DH * DOUT]; // 8KB
    for (int i = threadIdx.x; i < DH * DOUT; i += blockDim.x) W2s[i] = W2[i];
    __syncthreads();

    int warp = (blockIdx.x * blockDim.x + threadIdx.x) >> 5;
    int lane = threadIdx.x & 31;
    if (warp >= n) return;

    int beg = g_rowptr[warp], end = g_rowptr[warp + 1];
    const uint2* h8 = (const uint2*)g_h1h;     // 8B granules; row = 32 granules
    float4 acc = make_float4(0.f, 0.f, 0.f, 0.f);
    acc_h4(acc, h8[(size_t)warp * 32 + lane]); // self (already *dinv[i])

    int e = beg;
    for (; e + 7 < end; e += 8) {
        int j0 = g_col[e],     j1 = g_col[e + 1], j2 = g_col[e + 2], j3 = g_col[e + 3];
        int j4 = g_col[e + 4], j5 = g_col[e + 5], j6 = g_col[e + 6], j7 = g_col[e + 7];
        uint2 v0 = h8[(size_t)j0 * 32 + lane];
        uint2 v1 = h8[(size_t)j1 * 32 + lane];
        uint2 v2 = h8[(size_t)j2 * 32 + lane];
        uint2 v3 = h8[(size_t)j3 * 32 + lane];
        uint2 v4 = h8[(size_t)j4 * 32 + lane];
        uint2 v5 = h8[(size_t)j5 * 32 + lane];
        uint2 v6 = h8[(size_t)j6 * 32 + lane];
        uint2 v7 = h8[(size_t)j7 * 32 + lane];
        acc_h4(acc, v0); acc_h4(acc, v1); acc_h4(acc, v2); acc_h4(acc, v3);
        acc_h4(acc, v4); acc_h4(acc, v5); acc_h4(acc, v6); acc_h4(acc, v7);
    }
    for (; e < end; e++) {
        int j = g_col[e];
        acc_h4(acc, h8[(size_t)j * 32 + lane]);
    }

    float di = g_dinv[warp];
    float4 b = ((const float4*)b1)[lane];
    float xs[4];
    xs[0] = fmaxf(fmaf(acc.x, di, b.x), 0.f);
    xs[1] = fmaxf(fmaf(acc.y, di, b.y), 0.f);
    xs[2] = fmaxf(fmaf(acc.z, di, b.z), 0.f);
    xs[3] = fmaxf(fmaf(acc.w, di, b.w), 0.f);

    // gemm2: register-resident a1 row; lane l owns k=4l..4l+3
    float4 c0 = make_float4(0,0,0,0), c1 = c0, c2 = c0, c3 = c0;
    int k0 = lane * 4;
    #pragma unroll
    for (int kk = 0; kk < 4; kk++) {
        const float4* wrow = (const float4*)(W2s + (k0 + kk) * DOUT);
        float s = xs[kk];
        float4 q0 = wrow[0], q1 = wrow[1], q2 = wrow[2], q3 = wrow[3];
        FMA4(c0, q0, s);
        FMA4(c1, q1, s);
        FMA4(c2, q2, s);
        FMA4(c3, q3, s);
    }
    float v[16] = {c0.x,c0.y,c0.z,c0.w, c1.x,c1.y,c1.z,c1.w,
                   c2.x,c2.y,c2.z,c2.w, c3.x,c3.y,c3.z,c3.w};
    #pragma unroll
    for (int off = 16; off >= 1; off >>= 1) {
        #pragma unroll
        for (int o = 0; o < 16; o++)
            v[o] += __shfl_xor_sync(0xffffffffu, v[o], off);
    }
    if (lane < 16)
        g_h2[(size_t)warp * DOUT + lane] = v[lane] * di;
}

// ------------------------------------------------------------------
// Agg2 + bias + log_softmax. Warp per node; two half-warps split edges,
// each unrolled x4.
__global__ void k_agg2(const float* __restrict__ b2, float* __restrict__ out, int n) {
    int warp = (blockIdx.x * blockDim.x + threadIdx.x) >> 5;
    int lane = threadIdx.x & 31;
    if (warp >= n) return;
    int c = lane & 15, half = lane >> 4;
    int beg = g_rowptr[warp], end = g_rowptr[warp + 1];
    float acc = (half == 0) ? g_h2[(size_t)warp * DOUT + c] : 0.f; // self
    int e = beg + half;
    for (; e + 6 < end; e += 8) {
        int j0 = g_col[e], j1 = g_col[e + 2], j2 = g_col[e + 4], j3 = g_col[e + 6];
        float u0 = g_h2[(size_t)j0 * DOUT + c];
        float u1 = g_h2[(size_t)j1 * DOUT + c];
        float u2 = g_h2[(size_t)j2 * DOUT + c];
        float u3 = g_h2[(size_t)j3 * DOUT + c];
        acc += (u0 + u1) + (u2 + u3);
    }
    for (; e < end; e += 2) {
        int j = g_col[e];
        acc += g_h2[(size_t)j * DOUT + c];
    }
    acc += __shfl_xor_sync(0xffffffffu, acc, 16);
    float di = g_dinv[warp];
    float logit = fmaf(acc, di, b2[c]);
    float m = logit;
    #pragma unroll
    for (int off = 8; off >= 1; off >>= 1)
        m = fmaxf(m, __shfl_xor_sync(0xffffffffu, m, off));
    float ex = expf(logit - m);
    float s = ex;
    #pragma unroll
    for (int off = 8; off >= 1; off >>= 1)
        s += __shfl_xor_sync(0xffffffffu, s, off);
    if (half == 0)
        out[(size_t)warp * DOUT + c] = logit - m - logf(s);
}

// ------------------------------------------------------------------
extern "C" void kernel_launch(void* const* d_in, const int* in_sizes, int n_in,
                              void* d_out, int out_size) {
    const float* x  = (const float*)d_in[0];
    const void*  ei = d_in[1];                 // int32 or int64, detected on device
    const float* W1 = (const float*)d_in[2];
    const float* b1 = (const float*)d_in[3];
    const float* W2 = (const float*)d_in[4];
    const float* b2 = (const float*)d_in[5];
    float* out = (float*)d_out;

    int n = in_sizes[0] / DIN;  // 100000
    int e = in_sizes[1] / 2;    // 1600000

    // graph build; k_fill at my launch slot #4 (the ncu capture window)
    k_init   <<<(n + 255) / 256, 256>>>((const int*)ei, e, n);
    k_degree <<<(e + 255) / 256, 256>>>(ei, e, n);
    int nb = (n + 1023) / 1024;
    k_scanall<<<nb, 1024>>>(n, nb);
    k_fill   <<<(e + 255) / 256, 256>>>(ei, e, n);   // <-- profiled

    // layer 1 GEMM (standalone — fused-with-fill measured slower)
    k_gemm1<<<(n + 127) / 128, 256>>>(x, W1, n);

    // fused layer-1 aggregation (fp16 gather) + layer-2 GEMM
    k_agg1_gemm2<<<(n + 7) / 8, 256>>>(b1, W2, n);

    // layer-2 aggregation + log_softmax
    k_agg2<<<(n + 7) / 8, 256>>>(b2, out, n);
}

// round 17
// speedup vs baseline: 1.2235x; 1.1036x over previous
#include <cuda_runtime.h>
#include <cuda_fp16.h>
#include <math.h>

#define DIN  128
#define DH   128
#define DOUT 16
#define NCAP 100352
#define ECAP 1600128

// ---- scratch (static __device__ per harness rules) ----
// INVARIANT: g_deg == 0 and g_blkflag == 0 at entry of every kernel_launch
// call (true at process start from BSS; restored by scanall / fill below).
__device__ int   g_deg[NCAP];
__device__ float g_dinv[NCAP];
__device__ int   g_rowptr[NCAP + 1];
__device__ int   g_cursor[NCAP];
__device__ int   g_col[ECAP];
__device__ volatile int g_blkagg[128];    // lookback sums  (VOLATILE — R15/16 bug)
__device__ volatile int g_blkflag[128];   // lookback flags (VOLATILE)
__device__ __align__(16) __half g_h1h[(size_t)NCAP * DH];  // x@W1 (UNSCALED), fp16
__device__ __align__(16) float  g_h2[(size_t)NCAP * DOUT]; // (a1@W2)*dinv[row]

union H4 { __half2 h2[2]; uint2 u; };   // 8B  (gather granule per lane)
union H8 { __half2 h2[4]; uint4 u; };   // 16B (store granule per thread)

// ------------------------------------------------------------------
// warp-collective dtype detect: one LDG + ballot. int64 edge_index has
// zero high words (indices < 1e5); int32 has random values at odd slots.
__device__ __forceinline__ int warp_is64(const int* __restrict__ ei32) {
    int lane = threadIdx.x & 31;
    int vhi = (lane < 16) ? ei32[2 * lane + 1] : 0;
    unsigned m = __ballot_sync(0xffffffffu, vhi != 0);
    return m == 0;
}

__device__ __forceinline__ int edge_at2(const void* ei, size_t pos, int is64) {
    if (is64) return (int)((const long long*)ei)[pos];
    return ((const int*)ei)[pos];
}

// ------------------------------------------------------------------
#define FMA4(acc, vec, scal) do { \
    (acc).x = fmaf((scal), (vec).x, (acc).x); \
    (acc).y = fmaf((scal), (vec).y, (acc).y); \
    (acc).z = fmaf((scal), (vec).z, (acc).z); \
    (acc).w = fmaf((scal), (vec).w, (acc).w); } while (0)

#define KC 32          // k-chunk size for GEMM1
#define DG_BLOCKS 256  // degree blocks placed FIRST in the fused grid

// Fused: blocks [0, DG_BLOCKS) do the degree histogram (g_deg starts 0
// by the invariant); the rest do GEMM1 (UNSCALED): h1h = fp16(x @ W1).
__global__ void __launch_bounds__(256, 1) k_deg_gemm1(const float* __restrict__ x,
                                                      const float* __restrict__ W1,
                                                      const void* __restrict__ ei,
                                                      int e, int n) {
    __shared__ float Ws[KC * DH];    // 16KB
    __shared__ float Xs[128 * KC];   // 16KB

    if (blockIdx.x < DG_BLOCKS) {
        int is64 = warp_is64((const int*)ei);
        int i0 = blockIdx.x * blockDim.x + threadIdx.x;
        int stride = DG_BLOCKS * blockDim.x;
        for (int i = i0; i < e; i += stride) {
            int d = edge_at2(ei, (size_t)e + i, is64);
            if ((unsigned)d < (unsigned)n) atomicAdd(&g_deg[d], 1);
        }
        return;
    }

    int row0 = (blockIdx.x - DG_BLOCKS) * 128;
    int tx = threadIdx.x & 15;
    int ty = threadIdx.x >> 4;
    float4 a0[8], a1[8];
    #pragma unroll
    for (int r = 0; r < 8; r++) { a0[r] = make_float4(0,0,0,0); a1[r] = make_float4(0,0,0,0); }

    const float4* W4 = (const float4*)W1;
    const float4* x4 = (const float4*)x;
    float4* Ws4 = (float4*)Ws;
    float4* Xs4 = (float4*)Xs;

    for (int kc = 0; kc < DIN / KC; kc++) {
        for (int i = threadIdx.x; i < KC * DH / 4; i += 256)
            Ws4[i] = W4[kc * (KC * DH / 4) + i];
        for (int i = threadIdx.x; i < 128 * KC / 4; i += 256) {
            int r = i >> 3, c = i & 7, gr = row0 + r;
            Xs4[i] = (gr < n) ? x4[(size_t)gr * 32 + kc * 8 + c]
                              : make_float4(0.f, 0.f, 0.f, 0.f);
        }
        __syncthreads();

        const float* wp = Ws + tx * 8;
        #pragma unroll
        for (int k = 0; k < KC; k++) {
            float4 wv0 = *(const float4*)(wp + k * 128);
            float4 wv1 = *(const float4*)(wp + k * 128 + 4);
            #pragma unroll
            for (int r = 0; r < 8; r++) {
                float xv = Xs[(ty * 8 + r) * KC + k];
                FMA4(a0[r], wv0, xv);
                FMA4(a1[r], wv1, xv);
            }
        }
        __syncthreads();
    }

    #pragma unroll
    for (int r = 0; r < 8; r++) {
        int row = row0 + ty * 8 + r;
        if (row < n) {
            H8 st;
            st.h2[0] = __floats2half2_rn(a0[r].x, a0[r].y);
            st.h2[1] = __floats2half2_rn(a0[r].z, a0[r].w);
            st.h2[2] = __floats2half2_rn(a1[r].x, a1[r].y);
            st.h2[3] = __floats2half2_rn(a1[r].z, a1[r].w);
            *(uint4*)(g_h1h + (size_t)row * DH + tx * 8) = st.u;
        }
    }
}

// ------------------------------------------------------------------
// Fused prefix-sum (parallel decoupled lookback, volatile agg+flag).
// Also RE-ZEROES g_deg after consuming it (restores entry invariant).
// 98 blocks of 1024, all resident on 148 SMs => spin is deadlock-free.
__global__ void k_scanall(int n, int nb) {
    __shared__ int s[1024];
    __shared__ int boff_sh;
    int bid = blockIdx.x, tid = threadIdx.x;
    int i = bid * 1024 + tid;
    int d = (i < n) ? g_deg[i] : 0;
    s[tid] = d;
    if (i < n) g_dinv[i] = rsqrtf((float)(d + 1)); // +1 self loop
    __syncthreads();
    for (int off = 1; off < 1024; off <<= 1) {
        int t = (tid >= off) ? s[tid - off] : 0;
        __syncthreads();
        s[tid] += t;
        __syncthreads();
    }
    int incl = s[tid];
    int blocksum = s[1023];
    __syncthreads();

    if (tid == 0) {
        g_blkagg[bid] = blocksum;   // volatile store
        __threadfence();
        g_blkflag[bid] = 1;         // volatile store
    }

    int part = 0;
    if (tid < bid) {
        while (g_blkflag[tid] == 0) { }   // volatile spin
        part = g_blkagg[tid];             // volatile load (NOT hoistable)
    }
    s[tid] = part;
    __syncthreads();
    for (int off = 512; off >= 1; off >>= 1) {
        if (tid < off) s[tid] += s[tid + off];
        __syncthreads();
    }
    if (tid == 0) boff_sh = s[0];
    __syncthreads();

    int boff = boff_sh;
    if (i < n) {
        int v = boff + incl - d;   // exclusive
        g_rowptr[i] = v;
        g_cursor[i] = v;
        g_deg[i] = 0;              // restore invariant (own index only)
    }
    if (bid == nb - 1 && tid == 1023) g_rowptr[n] = boff + blocksum;
}

// ------------------------------------------------------------------
// CSR fill; block 0 also re-zeroes the lookback flags (scanall is done
// with them by the kernel boundary), restoring the entry invariant.
__global__ void k_fill(const void* __restrict__ ei, int e, int n) {
    if (blockIdx.x == 0 && threadIdx.x < 128) g_blkflag[threadIdx.x] = 0;
    int is64 = warp_is64((const int*)ei);
    int i = blockIdx.x * blockDim.x + threadIdx.x;
    if (i < e) {
        int s = edge_at2(ei, (size_t)i, is64);
        int d = edge_at2(ei, (size_t)e + i, is64);
        if ((unsigned)s < (unsigned)n && (unsigned)d < (unsigned)n) {
            int p = atomicAdd(&g_cursor[d], 1);
            if ((unsigned)p < (unsigned)ECAP) g_col[p] = s;
        }
    }
}

// ------------------------------------------------------------------
// Fused Agg1 + GEMM2: warp per node, fp16 gather scaled by dinv[j], x4 unroll.
__device__ __forceinline__ void fma_h4(float4& acc, uint2 raw, float sc) {
    H4 t; t.u = raw;
    float2 f0 = __half22float2(t.h2[0]);
    float2 f1 = __half22float2(t.h2[1]);
    acc.x = fmaf(sc, f0.x, acc.x); acc.y = fmaf(sc, f0.y, acc.y);
    acc.z = fmaf(sc, f1.x, acc.z); acc.w = fmaf(sc, f1.y, acc.w);
}

__global__ void __launch_bounds__(256) k_agg1_gemm2(const float* __restrict__ b1,
                                                    const float* __restrict__ W2, int n) {
    __shared__ float W2s[DH * DOUT]; // 8KB
    for (int i = threadIdx.x; i < DH * DOUT; i += blockDim.x) W2s[i] = W2[i];
    __syncthreads();

    int warp = (blockIdx.x * blockDim.x + threadIdx.x) >> 5;
    int lane = threadIdx.x & 31;
    if (warp >= n) return;

    int beg = g_rowptr[warp], end = g_rowptr[warp + 1];
    const uint2* h8 = (const uint2*)g_h1h;     // 8B granules; row = 32 granules
    float di = g_dinv[warp];
    float4 acc = make_float4(0.f, 0.f, 0.f, 0.f);
    fma_h4(acc, h8[(size_t)warp * 32 + lane], di);   // self term

    int e = beg;
    for (; e + 3 < end; e += 4) {
        int j0 = g_col[e], j1 = g_col[e + 1], j2 = g_col[e + 2], j3 = g_col[e + 3];
        float d0 = g_dinv[j0], d1 = g_dinv[j1], d2 = g_dinv[j2], d3 = g_dinv[j3];
        uint2 v0 = h8[(size_t)j0 * 32 + lane];
        uint2 v1 = h8[(size_t)j1 * 32 + lane];
        uint2 v2 = h8[(size_t)j2 * 32 + lane];
        uint2 v3 = h8[(size_t)j3 * 32 + lane];
        fma_h4(acc, v0, d0); fma_h4(acc, v1, d1);
        fma_h4(acc, v2, d2); fma_h4(acc, v3, d3);
    }
    for (; e < end; e++) {
        int j = g_col[e];
        fma_h4(acc, h8[(size_t)j * 32 + lane], g_dinv[j]);
    }

    float4 b = ((const float4*)b1)[lane];
    float xs[4];
    xs[0] = fmaxf(fmaf(acc.x, di, b.x), 0.f);
    xs[1] = fmaxf(fmaf(acc.y, di, b.y), 0.f);
    xs[2] = fmaxf(fmaf(acc.z, di, b.z), 0.f);
    xs[3] = fmaxf(fmaf(acc.w, di, b.w), 0.f);

    // gemm2: register-resident a1 row; lane l owns k=4l..4l+3
    float4 c0 = make_float4(0,0,0,0), c1 = c0, c2 = c0, c3 = c0;
    int k0 = lane * 4;
    #pragma unroll
    for (int kk = 0; kk < 4; kk++) {
        const float4* wrow = (const float4*)(W2s + (k0 + kk) * DOUT);
        float s = xs[kk];
        float4 q0 = wrow[0], q1 = wrow[1], q2 = wrow[2], q3 = wrow[3];
        FMA4(c0, q0, s);
        FMA4(c1, q1, s);
        FMA4(c2, q2, s);
        FMA4(c3, q3, s);
    }
    float v[16] = {c0.x,c0.y,c0.z,c0.w, c1.x,c1.y,c1.z,c1.w,
                   c2.x,c2.y,c2.z,c2.w, c3.x,c3.y,c3.z,c3.w};
    #pragma unroll
    for (int off = 16; off >= 1; off >>= 1) {
        #pragma unroll
        for (int o = 0; o < 16; o++)
            v[o] += __shfl_xor_sync(0xffffffffu, v[o], off);
    }
    if (lane < 16)
        g_h2[(size_t)warp * DOUT + lane] = v[lane] * di;
}

// ------------------------------------------------------------------
// Agg2 + bias + log_softmax. Warp per node; two half-warps split edges.
__global__ void k_agg2(const float* __restrict__ b2, float* __restrict__ out, int n) {
    int warp = (blockIdx.x * blockDim.x + threadIdx.x) >> 5;
    int lane = threadIdx.x & 31;
    if (warp >= n) return;
    int c = lane & 15, half = lane >> 4;
    int beg = g_rowptr[warp], end = g_rowptr[warp + 1];
    float acc = (half == 0) ? g_h2[(size_t)warp * DOUT + c] : 0.f; // self
    int e = beg + half;
    for (; e + 6 < end; e += 8) {
        int j0 = g_col[e], j1 = g_col[e + 2], j2 = g_col[e + 4], j3 = g_col[e + 6];
        float u0 = g_h2[(size_t)j0 * DOUT + c];
        float u1 = g_h2[(size_t)j1 * DOUT + c];
        float u2 = g_h2[(size_t)j2 * DOUT + c];
        float u3 = g_h2[(size_t)j3 * DOUT + c];
        acc += (u0 + u1) + (u2 + u3);
    }
    for (; e < end; e += 2) {
        int j = g_col[e];
        acc += g_h2[(size_t)j * DOUT + c];
    }
    acc += __shfl_xor_sync(0xffffffffu, acc, 16);
    float di = g_dinv[warp];
    float logit = fmaf(acc, di, b2[c]);
    float m = logit;
    #pragma unroll
    for (int off = 8; off >= 1; off >>= 1)
        m = fmaxf(m, __shfl_xor_sync(0xffffffffu, m, off));
    float ex = expf(logit - m);
    float s = ex;
    #pragma unroll
    for (int off = 8; off >= 1; off >>= 1)
        s += __shfl_xor_sync(0xffffffffu, s, off);
    if (half == 0)
        out[(size_t)warp * DOUT + c] = logit - m - logf(s);
}

// ------------------------------------------------------------------
extern "C" void kernel_launch(void* const* d_in, const int* in_sizes, int n_in,
                              void* d_out, int out_size) {
    const float* x  = (const float*)d_in[0];
    const void*  ei = d_in[1];                 // int32 or int64, detected per-warp
    const float* W1 = (const float*)d_in[2];
    const float* b1 = (const float*)d_in[3];
    const float* W2 = (const float*)d_in[4];
    const float* b2 = (const float*)d_in[5];
    float* out = (float*)d_out;

    int n = in_sizes[0] / DIN;  // 100000
    int e = in_sizes[1] / 2;    // 1600000

    int g1 = (n + 127) / 128;
    int nb = (n + 1023) / 1024;

    // 1: fused degree + GEMM1 (deg starts 0 by invariant; unscaled h1)
    k_deg_gemm1<<<DG_BLOCKS + g1, 256>>>(x, W1, ei, e, n);
    // 2: prefix sums (dinv/rowptr/cursor) + restore deg==0
    k_scanall<<<nb, 1024>>>(n, nb);
    // 3: CSR fill + restore flags==0
    k_fill<<<(e + 255) / 256, 256>>>(ei, e, n);
    // 4: fused agg1 + gemm2  <-- ncu profile window
    k_agg1_gemm2<<<(n + 7) / 8, 256>>>(b1, W2, n);
    // 5: agg2 + log_softmax
    k_agg2<<<(n + 7) / 8, 256>>>(b2, out, n);
}